// round 8
// baseline (speedup 1.0000x reference)
#include <cuda_runtime.h>
#include <cuda_fp16.h>

#define N0V   8192
#define N1V   100000
#define N2V   300000
#define KNBR  32
#define DD    64

typedef unsigned long long u64t;

#define PACKU64(out, lo, hi)  asm("mov.b64 %0, {%1, %2};" : "=l"(out) : "f"(lo), "f"(hi))
#define SPLATF64(out, v)      asm("mov.b64 %0, {%1, %1};" : "=l"(out) : "f"(v))
#define UNPACKF64(lo, hi, in) asm("mov.b64 {%0, %1}, %2;" : "=f"(lo), "=f"(hi) : "l"(in))
#define FFMA2(acc, a, b)      asm("fma.rn.f32x2 %0, %1, %2, %0;" : "+l"(acc) : "l"(a), "l"(b))

// Scratch (device globals — allocation in kernel_launch is forbidden).
__device__ __half g_v2h[(size_t)N2V * DD];    // 38.4 MB gather target
__device__ __half g_h1h[(size_t)N1V * DD];    // 12.8 MB hop-1 activations

// ---------------------------------------------------------------------------
// K1: v2h = half(feats[node_ids2]); 2 rows per thread for MLP.
// ---------------------------------------------------------------------------
__global__ void gather_v2h_kernel(const float* __restrict__ feats,
                                  const int*   __restrict__ node_ids2)
{
    int t = blockIdx.x * blockDim.x + threadIdx.x;
    const int half_total = (N2V / 2) * (DD / 4);
    if (t >= half_total) return;
    int row  = t >> 4;
    int c    = t & 15;
    int row2 = row + N2V / 2;
    int s1 = __ldg(node_ids2 + row);
    int s2 = __ldg(node_ids2 + row2);
    float4 v1 = __ldg((const float4*)(feats + (size_t)s1 * DD) + c);
    float4 v2 = __ldg((const float4*)(feats + (size_t)s2 * DD) + c);

    __half2 a0 = __floats2half2_rn(v1.x, v1.y);
    __half2 a1 = __floats2half2_rn(v1.z, v1.w);
    __half2 b0 = __floats2half2_rn(v2.x, v2.y);
    __half2 b1 = __floats2half2_rn(v2.z, v2.w);
    uint2 p1, p2;
    p1.x = *(unsigned int*)&a0;  p1.y = *(unsigned int*)&a1;
    p2.x = *(unsigned int*)&b0;  p2.y = *(unsigned int*)&b1;
    ((uint2*)g_v2h)[(size_t)row  * 16 + c] = p1;
    ((uint2*)g_v2h)[(size_t)row2 * 16 + c] = p2;
}

// ---------------------------------------------------------------------------
// Fused wide-gather mean + GEMM + bias + ReLU.
// Block = 256 threads = 8 warps x 4 rows = 32 output rows.
//
// Phase 1 (per warp, 4 rows): lane = (sub = lane>>3, ch = lane&7).
//   One LDG.128 fetches chunk `ch` of neighbor (4i+sub): 8 wide loads per row,
//   32 in flight per warp. fp16 accumulation (two interleaved sets, depth<=4),
//   merge + cvt to fp32, butterfly over the 4 subgroups (xor 8,16), scale by
//   1/32, sub s writes row s into sAgg[32][72] fp32.
// Phase 2: 32x64 GEMM from sAgg vs sW, f32x2 FMAs; thread = 1 row x 8 cols.
// ---------------------------------------------------------------------------
template<bool HALF_OUT>
__global__ void __launch_bounds__(256) fused_agg_gemm_kernel(
    const uint4* __restrict__ vsrc,    // [nsrc] rows of 8 x uint4 (128B fp16)
    const int*   __restrict__ nbr,     // [nrows][KNBR]
    const float* __restrict__ W,       // [DD][DD] row-major
    const float* __restrict__ bias,    // [DD]
    void*        __restrict__ outp,    // [nrows][DD] half or float
    int nrows)
{
    __shared__ float sW[DD * DD];      // 16 KB
    __shared__ float sAgg[32][72];     // 9 KB, stride 72 (conflict-free)

    const int tid  = threadIdx.x;
    const int lane = tid & 31;
    const int warp = tid >> 5;

    // Stage W (coalesced float4; pure L2 hits after block 0).
    #pragma unroll
    for (int i = tid; i < DD * DD / 4; i += 256)
        ((float4*)sW)[i] = __ldg((const float4*)W + i);

    // ---------------- Phase 1: wide-gather mean ----------------
    const int rowbase = blockIdx.x * 32 + warp * 4;
    const int sub = lane >> 3;
    const int ch  = lane & 7;

    int idx[4];
    #pragma unroll
    for (int r = 0; r < 4; ++r)
        idx[r] = __ldg(nbr + (size_t)min(rowbase + r, nrows - 1) * KNBR + lane);

    __half2 zero = __float2half2_rn(0.f);
    __half2 acc[4][2][4];
    #pragma unroll
    for (int r = 0; r < 4; ++r)
        #pragma unroll
        for (int s = 0; s < 2; ++s)
            #pragma unroll
            for (int j = 0; j < 4; ++j) acc[r][s][j] = zero;

    #pragma unroll
    for (int i = 0; i < 8; ++i) {
        #pragma unroll
        for (int r = 0; r < 4; ++r) {
            int n = __shfl_sync(0xffffffffu, idx[r], 4 * i + sub);
            uint4 d = __ldg(vsrc + (size_t)n * 8 + ch);
            const __half2* h = (const __half2*)&d;
            int s = i & 1;
            #pragma unroll
            for (int j = 0; j < 4; ++j)
                acc[r][s][j] = __hadd2(acc[r][s][j], h[j]);
        }
    }

    const float inv = 1.0f / KNBR;
    #pragma unroll
    for (int r = 0; r < 4; ++r) {
        float f[8];
        #pragma unroll
        for (int j = 0; j < 4; ++j) {
            float2 v = __half22float2(__hadd2(acc[r][0][j], acc[r][1][j]));
            f[2 * j] = v.x;  f[2 * j + 1] = v.y;
        }
        #pragma unroll
        for (int d = 8; d <= 16; d <<= 1)
            #pragma unroll
            for (int j = 0; j < 8; ++j)
                f[j] += __shfl_xor_sync(0xffffffffu, f[j], d);
        if (sub == r) {
            int lr = warp * 4 + r;
            *(float4*)&sAgg[lr][ch * 8]     =
                make_float4(f[0] * inv, f[1] * inv, f[2] * inv, f[3] * inv);
            *(float4*)&sAgg[lr][ch * 8 + 4] =
                make_float4(f[4] * inv, f[5] * inv, f[6] * inv, f[7] * inv);
        }
    }
    __syncthreads();

    // ---------------- Phase 2: GEMM + bias + ReLU ----------------
    const int rp   = tid >> 3;        // 0..31: local row
    const int col0 = (tid & 7) * 8;   // 8 consecutive output cols

    float4 bv0 = __ldg((const float4*)(bias + col0));
    float4 bv1 = __ldg((const float4*)(bias + col0 + 4));
    u64t a0, a1, a2, a3;
    PACKU64(a0, bv0.x, bv0.y);  PACKU64(a1, bv0.z, bv0.w);
    PACKU64(a2, bv1.x, bv1.y);  PACKU64(a3, bv1.z, bv1.w);

    #pragma unroll
    for (int k = 0; k < DD; ++k) {
        float av = sAgg[rp][k];
        u64t s;
        SPLATF64(s, av);
        const ulonglong2 w01 = *(const ulonglong2*)&sW[k * DD + col0];
        const ulonglong2 w23 = *(const ulonglong2*)&sW[k * DD + col0 + 4];
        FFMA2(a0, s, w01.x);  FFMA2(a1, s, w01.y);
        FFMA2(a2, s, w23.x);  FFMA2(a3, s, w23.y);
    }

    const int grow = blockIdx.x * 32 + rp;
    if (grow < nrows) {
        float o[8];
        float lo, hi;
        UNPACKF64(lo, hi, a0);  o[0] = fmaxf(lo, 0.f);  o[1] = fmaxf(hi, 0.f);
        UNPACKF64(lo, hi, a1);  o[2] = fmaxf(lo, 0.f);  o[3] = fmaxf(hi, 0.f);
        UNPACKF64(lo, hi, a2);  o[4] = fmaxf(lo, 0.f);  o[5] = fmaxf(hi, 0.f);
        UNPACKF64(lo, hi, a3);  o[6] = fmaxf(lo, 0.f);  o[7] = fmaxf(hi, 0.f);
        if (HALF_OUT) {
            __half2 h[4];
            #pragma unroll
            for (int j = 0; j < 4; ++j) h[j] = __floats2half2_rn(o[2 * j], o[2 * j + 1]);
            *(uint4*)((__half*)outp + (size_t)grow * DD + col0) = *(uint4*)h;
        } else {
            float* op = (float*)outp + (size_t)grow * DD + col0;
            *(float4*)op       = make_float4(o[0], o[1], o[2], o[3]);
            *(float4*)(op + 4) = make_float4(o[4], o[5], o[6], o[7]);
        }
    }
}

// ---------------------------------------------------------------------------
// Inputs: 0 feats, 1 W0, 2 b0, 3 W1, 4 b1, 5 neigh_idx0, 6 neigh_idx1,
//         7 node_ids1 (unused), 8 node_ids2
// ---------------------------------------------------------------------------
extern "C" void kernel_launch(void* const* d_in, const int* in_sizes, int n_in,
                              void* d_out, int out_size)
{
    const float* feats      = (const float*)d_in[0];
    const float* W0         = (const float*)d_in[1];
    const float* b0         = (const float*)d_in[2];
    const float* W1         = (const float*)d_in[3];
    const float* b1         = (const float*)d_in[4];
    const int*   neigh_idx0 = (const int*)  d_in[5];
    const int*   neigh_idx1 = (const int*)  d_in[6];
    const int*   node_ids2  = (const int*)  d_in[8];
    float*       out        = (float*)d_out;

    __half* v2h; cudaGetSymbolAddress((void**)&v2h, g_v2h);
    __half* h1h; cudaGetSymbolAddress((void**)&h1h, g_h1h);

    {
        const int half_total = (N2V / 2) * (DD / 4);
        gather_v2h_kernel<<<(half_total + 255) / 256, 256>>>(feats, node_ids2);
    }
    // Hop-1: h1 = relu(mean(v2[neigh_idx1]) @ W0 + b0)   (fp16 out)
    fused_agg_gemm_kernel<true ><<<(N1V + 31) / 32, 256>>>(
        (const uint4*)v2h, neigh_idx1, W0, b0, (void*)h1h, N1V);
    // Seed: out = relu(mean(h1[neigh_idx0]) @ W1 + b1)   (fp32 out)
    fused_agg_gemm_kernel<false><<<(N0V + 31) / 32, 256>>>(
        (const uint4*)h1h, neigh_idx0, W1, b1, (void*)out, N0V);
}

// round 9
// speedup vs baseline: 1.5633x; 1.5633x over previous
#include <cuda_runtime.h>
#include <cuda_fp16.h>

#define N0V   8192
#define N1V   100000
#define N2V   300000
#define KNBR  32
#define DD    64

typedef unsigned long long u64t;

#define PACKU64(out, lo, hi)  asm("mov.b64 %0, {%1, %2};" : "=l"(out) : "f"(lo), "f"(hi))
#define SPLATF64(out, v)      asm("mov.b64 %0, {%1, %1};" : "=l"(out) : "f"(v))
#define UNPACKF64(lo, hi, in) asm("mov.b64 {%0, %1}, %2;" : "=f"(lo), "=f"(hi) : "l"(in))
#define FFMA2(acc, a, b)      asm("fma.rn.f32x2 %0, %1, %2, %0;" : "+l"(acc) : "l"(a), "l"(b))

// Scratch (device globals — allocation in kernel_launch is forbidden).
__device__ __half g_v2h[(size_t)N2V * DD];    // 38.4 MB gather target
__device__ __half g_agg1[(size_t)N1V * DD];   // 12.8 MB hop-1 aggregates
__device__ __half g_h1h[(size_t)N1V * DD];    // 12.8 MB hop-1 activations

// ---------------------------------------------------------------------------
// K1: v2h = half(feats[node_ids2]); 2 rows per thread for MLP.
// ---------------------------------------------------------------------------
__global__ void gather_v2h_kernel(const float* __restrict__ feats,
                                  const int*   __restrict__ node_ids2)
{
    int t = blockIdx.x * blockDim.x + threadIdx.x;
    const int half_total = (N2V / 2) * (DD / 4);
    if (t >= half_total) return;
    int row  = t >> 4;
    int c    = t & 15;
    int row2 = row + N2V / 2;
    int s1 = __ldg(node_ids2 + row);
    int s2 = __ldg(node_ids2 + row2);
    float4 v1 = __ldg((const float4*)(feats + (size_t)s1 * DD) + c);
    float4 v2 = __ldg((const float4*)(feats + (size_t)s2 * DD) + c);

    __half2 a0 = __floats2half2_rn(v1.x, v1.y);
    __half2 a1 = __floats2half2_rn(v1.z, v1.w);
    __half2 b0 = __floats2half2_rn(v2.x, v2.y);
    __half2 b1 = __floats2half2_rn(v2.z, v2.w);
    uint2 p1, p2;
    p1.x = *(unsigned int*)&a0;  p1.y = *(unsigned int*)&a1;
    p2.x = *(unsigned int*)&b0;  p2.y = *(unsigned int*)&b1;
    ((uint2*)g_v2h)[(size_t)row  * 16 + c] = p1;
    ((uint2*)g_v2h)[(size_t)row2 * 16 + c] = p2;
}

// ---------------------------------------------------------------------------
// K2: pure gather-mean, wide-load variant (R7, unchanged — validated).
// Warp handles 2 rows; LDG.128 fetches 4 whole neighbor rows.
// ---------------------------------------------------------------------------
__global__ void __launch_bounds__(256) agg_mean_kernel(
    const uint4* __restrict__ vsrc,    // [nsrc] rows of 8 x uint4 (128B)
    const int*   __restrict__ nbr,     // [nrows][KNBR]
    __half*      __restrict__ aggout,  // [nrows][DD] fp16
    int nrows)
{
    const int tid  = threadIdx.x;
    const int lane = tid & 31;
    const int warp = tid >> 5;
    const int rowA = blockIdx.x * 16 + warp * 2;
    const int rowB = rowA + 1;
    const int crA = min(rowA, nrows - 1);
    const int crB = min(rowB, nrows - 1);

    const int idxA = __ldg(nbr + (size_t)crA * KNBR + lane);
    const int idxB = __ldg(nbr + (size_t)crB * KNBR + lane);

    const int sub = lane >> 3;
    const int ch  = lane & 7;

    __half2 zero = __float2half2_rn(0.f);
    __half2 aAcc[2][4], bAcc[2][4];
    #pragma unroll
    for (int s = 0; s < 2; ++s)
        #pragma unroll
        for (int j = 0; j < 4; ++j) { aAcc[s][j] = zero; bAcc[s][j] = zero; }

    #pragma unroll
    for (int i = 0; i < 8; ++i) {
        int nA = __shfl_sync(0xffffffffu, idxA, 4 * i + sub);
        int nB = __shfl_sync(0xffffffffu, idxB, 4 * i + sub);
        uint4 dA = __ldg(vsrc + (size_t)nA * 8 + ch);
        uint4 dB = __ldg(vsrc + (size_t)nB * 8 + ch);
        const __half2* hA = (const __half2*)&dA;
        const __half2* hB = (const __half2*)&dB;
        int s = i & 1;
        #pragma unroll
        for (int j = 0; j < 4; ++j) {
            aAcc[s][j] = __hadd2(aAcc[s][j], hA[j]);
            bAcc[s][j] = __hadd2(bAcc[s][j], hB[j]);
        }
    }

    float fA[8], fB[8];
    #pragma unroll
    for (int j = 0; j < 4; ++j) {
        float2 va = __half22float2(__hadd2(aAcc[0][j], aAcc[1][j]));
        float2 vb = __half22float2(__hadd2(bAcc[0][j], bAcc[1][j]));
        fA[2 * j] = va.x;  fA[2 * j + 1] = va.y;
        fB[2 * j] = vb.x;  fB[2 * j + 1] = vb.y;
    }

    #pragma unroll
    for (int d = 8; d <= 16; d <<= 1) {
        #pragma unroll
        for (int j = 0; j < 8; ++j) {
            fA[j] += __shfl_xor_sync(0xffffffffu, fA[j], d);
            fB[j] += __shfl_xor_sync(0xffffffffu, fB[j], d);
        }
    }

    const float inv = 1.0f / KNBR;
    if (sub == 0 && rowA < nrows) {
        __half2 h[4];
        #pragma unroll
        for (int j = 0; j < 4; ++j)
            h[j] = __floats2half2_rn(fA[2 * j] * inv, fA[2 * j + 1] * inv);
        ((uint4*)aggout)[(size_t)rowA * 8 + ch] = *(uint4*)h;
    }
    if (sub == 1 && rowB < nrows) {
        __half2 h[4];
        #pragma unroll
        for (int j = 0; j < 4; ++j)
            h[j] = __floats2half2_rn(fB[2 * j] * inv, fB[2 * j + 1] * inv);
        ((uint4*)aggout)[(size_t)rowB * 8 + ch] = *(uint4*)h;
    }
}

// ---------------------------------------------------------------------------
// K3: pure GEMM  out = relu(A @ W + b)  (R7, unchanged — validated).
// ---------------------------------------------------------------------------
__global__ void __launch_bounds__(256) gemm64_kernel(
    const __half* __restrict__ A,
    const float*  __restrict__ W,
    const float*  __restrict__ bias,
    __half*       __restrict__ out,
    int nrows)
{
    __shared__ float  sW[DD * DD];
    __shared__ __half sA[128 * 72];

    const int tid = threadIdx.x;
    #pragma unroll
    for (int i = tid; i < DD * DD / 4; i += 256)
        ((float4*)sW)[i] = __ldg((const float4*)W + i);

    const int rowbase = blockIdx.x * 128;
    for (int i = tid; i < 1024; i += 256) {
        int r = i >> 3, c = i & 7;
        int gr = min(rowbase + r, nrows - 1);
        uint4 v = __ldg((const uint4*)(A + (size_t)gr * DD) + c);
        *(uint4*)&sA[r * 72 + c * 8] = v;
    }
    __syncthreads();

    const int rp   = tid >> 3;
    const int col0 = (tid & 7) * 8;

    float4 bv0 = __ldg((const float4*)(bias + col0));
    float4 bv1 = __ldg((const float4*)(bias + col0 + 4));
    u64t bp[4];
    PACKU64(bp[0], bv0.x, bv0.y);  PACKU64(bp[1], bv0.z, bv0.w);
    PACKU64(bp[2], bv1.x, bv1.y);  PACKU64(bp[3], bv1.z, bv1.w);
    u64t acc[4][4];
    #pragma unroll
    for (int r = 0; r < 4; ++r)
        #pragma unroll
        for (int j = 0; j < 4; ++j) acc[r][j] = bp[j];

    #pragma unroll
    for (int k = 0; k < DD; k += 2) {
        ulonglong2 wA01 = *(const ulonglong2*)&sW[k * DD + col0];
        ulonglong2 wA23 = *(const ulonglong2*)&sW[k * DD + col0 + 4];
        ulonglong2 wB01 = *(const ulonglong2*)&sW[(k + 1) * DD + col0];
        ulonglong2 wB23 = *(const ulonglong2*)&sW[(k + 1) * DD + col0 + 4];
        #pragma unroll
        for (int r = 0; r < 4; ++r) {
            __half2 ah = *(const __half2*)&sA[(4 * rp + r) * 72 + k];
            float2 af = __half22float2(ah);
            u64t s0, s1;
            SPLATF64(s0, af.x);
            SPLATF64(s1, af.y);
            FFMA2(acc[r][0], s0, wA01.x);  FFMA2(acc[r][1], s0, wA01.y);
            FFMA2(acc[r][2], s0, wA23.x);  FFMA2(acc[r][3], s0, wA23.y);
            FFMA2(acc[r][0], s1, wB01.x);  FFMA2(acc[r][1], s1, wB01.y);
            FFMA2(acc[r][2], s1, wB23.x);  FFMA2(acc[r][3], s1, wB23.y);
        }
    }

    #pragma unroll
    for (int r = 0; r < 4; ++r) {
        int grow = rowbase + 4 * rp + r;
        if (grow >= nrows) continue;
        __half2 h[4];
        #pragma unroll
        for (int j = 0; j < 4; ++j) {
            float lo, hi;
            UNPACKF64(lo, hi, acc[r][j]);
            h[j] = __floats2half2_rn(fmaxf(lo, 0.f), fmaxf(hi, 0.f));
        }
        *(uint4*)(out + (size_t)grow * DD + col0) = *(uint4*)h;
    }
}

// ---------------------------------------------------------------------------
// K4: seed layer, fused wide-gather mean + GEMM (fp16 in, fp32 out).
// Block = 256 threads = 8 warps x 4 rows = 32 rows -> grid 256 for 8192.
// Source (g_h1h, 12.8MB) is L2-resident; W-staging only 256 blocks.
// ---------------------------------------------------------------------------
__global__ void __launch_bounds__(256) seed_fused_kernel(
    const uint4* __restrict__ vsrc,    // [nsrc] rows of 8 x uint4 (128B fp16)
    const int*   __restrict__ nbr,     // [nrows][KNBR]
    const float* __restrict__ W,       // [DD][DD] row-major
    const float* __restrict__ bias,    // [DD]
    float*       __restrict__ outp,    // [nrows][DD] fp32
    int nrows)
{
    __shared__ float sW[DD * DD];      // 16 KB
    __shared__ float sAgg[32][72];     // 9 KB

    const int tid  = threadIdx.x;
    const int lane = tid & 31;
    const int warp = tid >> 5;

    #pragma unroll
    for (int i = tid; i < DD * DD / 4; i += 256)
        ((float4*)sW)[i] = __ldg((const float4*)W + i);

    const int rowbase = blockIdx.x * 32 + warp * 4;
    const int sub = lane >> 3;
    const int ch  = lane & 7;

    int idx[4];
    #pragma unroll
    for (int r = 0; r < 4; ++r)
        idx[r] = __ldg(nbr + (size_t)min(rowbase + r, nrows - 1) * KNBR + lane);

    __half2 zero = __float2half2_rn(0.f);
    __half2 acc[4][2][4];
    #pragma unroll
    for (int r = 0; r < 4; ++r)
        #pragma unroll
        for (int s = 0; s < 2; ++s)
            #pragma unroll
            for (int j = 0; j < 4; ++j) acc[r][s][j] = zero;

    #pragma unroll
    for (int i = 0; i < 8; ++i) {
        #pragma unroll
        for (int r = 0; r < 4; ++r) {
            int n = __shfl_sync(0xffffffffu, idx[r], 4 * i + sub);
            uint4 d = __ldg(vsrc + (size_t)n * 8 + ch);
            const __half2* h = (const __half2*)&d;
            int s = i & 1;
            #pragma unroll
            for (int j = 0; j < 4; ++j)
                acc[r][s][j] = __hadd2(acc[r][s][j], h[j]);
        }
    }

    const float inv = 1.0f / KNBR;
    #pragma unroll
    for (int r = 0; r < 4; ++r) {
        float f[8];
        #pragma unroll
        for (int j = 0; j < 4; ++j) {
            float2 v = __half22float2(__hadd2(acc[r][0][j], acc[r][1][j]));
            f[2 * j] = v.x;  f[2 * j + 1] = v.y;
        }
        #pragma unroll
        for (int d = 8; d <= 16; d <<= 1)
            #pragma unroll
            for (int j = 0; j < 8; ++j)
                f[j] += __shfl_xor_sync(0xffffffffu, f[j], d);
        if (sub == r) {
            int lr = warp * 4 + r;
            *(float4*)&sAgg[lr][ch * 8]     =
                make_float4(f[0] * inv, f[1] * inv, f[2] * inv, f[3] * inv);
            *(float4*)&sAgg[lr][ch * 8 + 4] =
                make_float4(f[4] * inv, f[5] * inv, f[6] * inv, f[7] * inv);
        }
    }
    __syncthreads();

    const int rp   = tid >> 3;
    const int col0 = (tid & 7) * 8;

    float4 bv0 = __ldg((const float4*)(bias + col0));
    float4 bv1 = __ldg((const float4*)(bias + col0 + 4));
    u64t a0, a1, a2, a3;
    PACKU64(a0, bv0.x, bv0.y);  PACKU64(a1, bv0.z, bv0.w);
    PACKU64(a2, bv1.x, bv1.y);  PACKU64(a3, bv1.z, bv1.w);

    #pragma unroll
    for (int k = 0; k < DD; ++k) {
        float av = sAgg[rp][k];
        u64t s;
        SPLATF64(s, av);
        const ulonglong2 w01 = *(const ulonglong2*)&sW[k * DD + col0];
        const ulonglong2 w23 = *(const ulonglong2*)&sW[k * DD + col0 + 4];
        FFMA2(a0, s, w01.x);  FFMA2(a1, s, w01.y);
        FFMA2(a2, s, w23.x);  FFMA2(a3, s, w23.y);
    }

    const int grow = blockIdx.x * 32 + rp;
    if (grow < nrows) {
        float* op = outp + (size_t)grow * DD + col0;
        float lo, hi;
        UNPACKF64(lo, hi, a0);  op[0] = fmaxf(lo, 0.f);  op[1] = fmaxf(hi, 0.f);
        UNPACKF64(lo, hi, a1);  op[2] = fmaxf(lo, 0.f);  op[3] = fmaxf(hi, 0.f);
        UNPACKF64(lo, hi, a2);  op[4] = fmaxf(lo, 0.f);  op[5] = fmaxf(hi, 0.f);
        UNPACKF64(lo, hi, a3);  op[6] = fmaxf(lo, 0.f);  op[7] = fmaxf(hi, 0.f);
    }
}

// ---------------------------------------------------------------------------
// Inputs: 0 feats, 1 W0, 2 b0, 3 W1, 4 b1, 5 neigh_idx0, 6 neigh_idx1,
//         7 node_ids1 (unused), 8 node_ids2
// ---------------------------------------------------------------------------
extern "C" void kernel_launch(void* const* d_in, const int* in_sizes, int n_in,
                              void* d_out, int out_size)
{
    const float* feats      = (const float*)d_in[0];
    const float* W0         = (const float*)d_in[1];
    const float* b0         = (const float*)d_in[2];
    const float* W1         = (const float*)d_in[3];
    const float* b1         = (const float*)d_in[4];
    const int*   neigh_idx0 = (const int*)  d_in[5];
    const int*   neigh_idx1 = (const int*)  d_in[6];
    const int*   node_ids2  = (const int*)  d_in[8];
    float*       out        = (float*)d_out;

    __half* v2h;  cudaGetSymbolAddress((void**)&v2h,  g_v2h);
    __half* agg1; cudaGetSymbolAddress((void**)&agg1, g_agg1);
    __half* h1h;  cudaGetSymbolAddress((void**)&h1h,  g_h1h);

    {
        const int half_total = (N2V / 2) * (DD / 4);
        gather_v2h_kernel<<<(half_total + 255) / 256, 256>>>(feats, node_ids2);
    }
    agg_mean_kernel<<<(N1V + 15) / 16, 256>>>(
        (const uint4*)v2h, neigh_idx1, agg1, N1V);
    gemm64_kernel<<<(N1V + 127) / 128, 256>>>(
        agg1, W0, b0, h1h, N1V);
    seed_fused_kernel<<<(N0V + 31) / 32, 256>>>(
        (const uint4*)h1h, neigh_idx0, W1, b1, out, N0V);
}

// round 10
// speedup vs baseline: 1.6647x; 1.0648x over previous
#include <cuda_runtime.h>
#include <cuda_fp16.h>
#include <mma.h>

using namespace nvcuda;

#define N0V   8192
#define N1V   100000
#define N2V   300000
#define KNBR  32
#define DD    64

// Scratch (device globals — allocation in kernel_launch is forbidden).
__device__ __half g_v2h[(size_t)N2V * DD];    // 38.4 MB gather target
__device__ __half g_agg1[(size_t)N1V * DD];   // 12.8 MB hop-1 aggregates
__device__ __half g_h1h[(size_t)N1V * DD];    // 12.8 MB hop-1 activations
__device__ __half g_agg0[(size_t)N0V * DD];   // 1 MB   seed aggregates
__device__ __half g_W0h[DD * DD];
__device__ __half g_W1h[DD * DD];

// ---------------------------------------------------------------------------
// K0: convert weights to fp16 once per call (tiny).
// ---------------------------------------------------------------------------
__global__ void convert_w_kernel(const float* __restrict__ W0,
                                 const float* __restrict__ W1)
{
    int i = blockIdx.x * blockDim.x + threadIdx.x;
    if (i < DD * DD) {
        g_W0h[i] = __float2half(W0[i]);
        g_W1h[i] = __float2half(W1[i]);
    }
}

// ---------------------------------------------------------------------------
// K1: v2h = half(feats[node_ids2]); 2 rows per thread for MLP.
// ---------------------------------------------------------------------------
__global__ void gather_v2h_kernel(const float* __restrict__ feats,
                                  const int*   __restrict__ node_ids2)
{
    int t = blockIdx.x * blockDim.x + threadIdx.x;
    const int half_total = (N2V / 2) * (DD / 4);
    if (t >= half_total) return;
    int row  = t >> 4;
    int c    = t & 15;
    int row2 = row + N2V / 2;
    int s1 = __ldg(node_ids2 + row);
    int s2 = __ldg(node_ids2 + row2);
    float4 v1 = __ldg((const float4*)(feats + (size_t)s1 * DD) + c);
    float4 v2 = __ldg((const float4*)(feats + (size_t)s2 * DD) + c);

    __half2 a0 = __floats2half2_rn(v1.x, v1.y);
    __half2 a1 = __floats2half2_rn(v1.z, v1.w);
    __half2 b0 = __floats2half2_rn(v2.x, v2.y);
    __half2 b1 = __floats2half2_rn(v2.z, v2.w);
    uint2 p1, p2;
    p1.x = *(unsigned int*)&a0;  p1.y = *(unsigned int*)&a1;
    p2.x = *(unsigned int*)&b0;  p2.y = *(unsigned int*)&b1;
    ((uint2*)g_v2h)[(size_t)row  * 16 + c] = p1;
    ((uint2*)g_v2h)[(size_t)row2 * 16 + c] = p2;
}

// ---------------------------------------------------------------------------
// Wide-load gather-mean (validated R7 structure).
// Warp handles 2 rows; LDG.128 fetches 4 whole neighbor rows.
// ---------------------------------------------------------------------------
__global__ void __launch_bounds__(256) agg_mean_kernel(
    const uint4* __restrict__ vsrc,    // [nsrc] rows of 8 x uint4 (128B)
    const int*   __restrict__ nbr,     // [nrows][KNBR]
    __half*      __restrict__ aggout,  // [nrows][DD] fp16
    int nrows)
{
    const int tid  = threadIdx.x;
    const int lane = tid & 31;
    const int warp = tid >> 5;
    const int rowA = blockIdx.x * 16 + warp * 2;
    const int rowB = rowA + 1;
    const int crA = min(rowA, nrows - 1);
    const int crB = min(rowB, nrows - 1);

    const int idxA = __ldg(nbr + (size_t)crA * KNBR + lane);
    const int idxB = __ldg(nbr + (size_t)crB * KNBR + lane);

    const int sub = lane >> 3;
    const int ch  = lane & 7;

    __half2 zero = __float2half2_rn(0.f);
    __half2 aAcc[2][4], bAcc[2][4];
    #pragma unroll
    for (int s = 0; s < 2; ++s)
        #pragma unroll
        for (int j = 0; j < 4; ++j) { aAcc[s][j] = zero; bAcc[s][j] = zero; }

    #pragma unroll
    for (int i = 0; i < 8; ++i) {
        int nA = __shfl_sync(0xffffffffu, idxA, 4 * i + sub);
        int nB = __shfl_sync(0xffffffffu, idxB, 4 * i + sub);
        uint4 dA = __ldg(vsrc + (size_t)nA * 8 + ch);
        uint4 dB = __ldg(vsrc + (size_t)nB * 8 + ch);
        const __half2* hA = (const __half2*)&dA;
        const __half2* hB = (const __half2*)&dB;
        int s = i & 1;
        #pragma unroll
        for (int j = 0; j < 4; ++j) {
            aAcc[s][j] = __hadd2(aAcc[s][j], hA[j]);
            bAcc[s][j] = __hadd2(bAcc[s][j], hB[j]);
        }
    }

    float fA[8], fB[8];
    #pragma unroll
    for (int j = 0; j < 4; ++j) {
        float2 va = __half22float2(__hadd2(aAcc[0][j], aAcc[1][j]));
        float2 vb = __half22float2(__hadd2(bAcc[0][j], bAcc[1][j]));
        fA[2 * j] = va.x;  fA[2 * j + 1] = va.y;
        fB[2 * j] = vb.x;  fB[2 * j + 1] = vb.y;
    }

    #pragma unroll
    for (int d = 8; d <= 16; d <<= 1) {
        #pragma unroll
        for (int j = 0; j < 8; ++j) {
            fA[j] += __shfl_xor_sync(0xffffffffu, fA[j], d);
            fB[j] += __shfl_xor_sync(0xffffffffu, fB[j], d);
        }
    }

    const float inv = 1.0f / KNBR;
    if (sub == 0 && rowA < nrows) {
        __half2 h[4];
        #pragma unroll
        for (int j = 0; j < 4; ++j)
            h[j] = __floats2half2_rn(fA[2 * j] * inv, fA[2 * j + 1] * inv);
        ((uint4*)aggout)[(size_t)rowA * 8 + ch] = *(uint4*)h;
    }
    if (sub == 1 && rowB < nrows) {
        __half2 h[4];
        #pragma unroll
        for (int j = 0; j < 4; ++j)
            h[j] = __floats2half2_rn(fB[2 * j] * inv, fB[2 * j + 1] * inv);
        ((uint4*)aggout)[(size_t)rowB * 8 + ch] = *(uint4*)h;
    }
}

// ---------------------------------------------------------------------------
// Tensor-core GEMM: out = relu(A @ W + b).  A fp16 [nrows,64], W fp16 64x64.
// Block = 256 threads = 8 warps x 16 rows = 128 rows.
// Bias enters as the initial accumulator (bias-replicated smem tile);
// ReLU applied elementwise on fragments.
// Dynamic smem: sA 128x72 half | sW 64x64 half | sBias 16x64 f32
//               [| sC 8x16x72 f32 when HALF_OUT]
// ---------------------------------------------------------------------------
#define SM_A     (128 * 72 * 2)              // 18432
#define SM_W     (DD * DD * 2)               // 8192
#define SM_BIAS  (16 * DD * 4)               // 4096
#define SM_C     (8 * 16 * 72 * 4)           // 36864
#define DYN_F    (SM_A + SM_W + SM_BIAS)            // 30720 (float out)
#define DYN_H    (SM_A + SM_W + SM_BIAS + SM_C)     // 67584 (half out)

template<bool HALF_OUT>
__global__ void __launch_bounds__(256) gemm_wmma_kernel(
    const __half* __restrict__ A,
    const __half* __restrict__ Wh,
    const float*  __restrict__ bias,
    void*         __restrict__ out,
    int nrows)
{
    extern __shared__ char dynsm[];
    __half* sA    = (__half*)dynsm;                        // [128][72]
    __half* sW    = (__half*)(dynsm + SM_A);               // [64][64]
    float*  sBias = (float*) (dynsm + SM_A + SM_W);        // [16][64]
    float*  sC    = (float*) (dynsm + SM_A + SM_W + SM_BIAS);

    const int tid  = threadIdx.x;
    const int lane = tid & 31;
    const int warp = tid >> 5;
    const int rowbase = blockIdx.x * 128;

    // Stage W (4096 halfs = 512 uint4).
    #pragma unroll
    for (int i = tid; i < 512; i += 256)
        ((uint4*)sW)[i] = __ldg((const uint4*)Wh + i);
    // Stage bias-replicated tile (16 rows x 64).
    for (int i = tid; i < 16 * DD; i += 256)
        sBias[i] = __ldg(bias + (i & (DD - 1)));
    // Stage A rows (clamped).
    for (int i = tid; i < 1024; i += 256) {
        int r = i >> 3, c = i & 7;
        int gr = min(rowbase + r, nrows - 1);
        uint4 v = __ldg((const uint4*)(A + (size_t)gr * DD) + c);
        *(uint4*)(sA + r * 72 + c * 8) = v;
    }
    __syncthreads();

    wmma::fragment<wmma::accumulator, 16, 16, 16, float> acc[4];
    #pragma unroll
    for (int n = 0; n < 4; ++n)
        wmma::load_matrix_sync(acc[n], sBias + n * 16, DD, wmma::mem_row_major);

    #pragma unroll
    for (int k = 0; k < 4; ++k) {
        wmma::fragment<wmma::matrix_a, 16, 16, 16, __half, wmma::row_major> a;
        wmma::load_matrix_sync(a, sA + (warp * 16) * 72 + k * 16, 72);
        #pragma unroll
        for (int n = 0; n < 4; ++n) {
            wmma::fragment<wmma::matrix_b, 16, 16, 16, __half, wmma::row_major> b;
            wmma::load_matrix_sync(b, sW + (k * 16) * DD + n * 16, DD);
            wmma::mma_sync(acc[n], a, b, acc[n]);
        }
    }

    // ReLU elementwise on fragments (column-independent, layout-safe).
    #pragma unroll
    for (int n = 0; n < 4; ++n)
        #pragma unroll
        for (int e = 0; e < acc[n].num_elements; ++e)
            acc[n].x[e] = fmaxf(acc[n].x[e], 0.f);

    if (HALF_OUT) {
        float* myC = sC + warp * 16 * 72;
        #pragma unroll
        for (int n = 0; n < 4; ++n)
            wmma::store_matrix_sync(myC + n * 16, acc[n], 72, wmma::mem_row_major);
        __syncwarp();
        // lane -> row (lane>>1), col-half (lane&1)*32; 32 halfs per lane.
        int r = lane >> 1;
        int c0 = (lane & 1) * 32;
        int grow = rowbase + warp * 16 + r;
        if (grow < nrows) {
            __half* op = (__half*)out + (size_t)grow * DD + c0;
            #pragma unroll
            for (int v = 0; v < 4; ++v) {
                float4 f0 = *(float4*)&myC[r * 72 + c0 + v * 8];
                float4 f1 = *(float4*)&myC[r * 72 + c0 + v * 8 + 4];
                __half2 h[4];
                h[0] = __floats2half2_rn(f0.x, f0.y);
                h[1] = __floats2half2_rn(f0.z, f0.w);
                h[2] = __floats2half2_rn(f1.x, f1.y);
                h[3] = __floats2half2_rn(f1.z, f1.w);
                *(uint4*)(op + v * 8) = *(uint4*)h;
            }
        }
    } else {
        // fp32: rows guaranteed in range when nrows % 128 == 0 (seed: 8192).
        int grow0 = rowbase + warp * 16;
        #pragma unroll
        for (int n = 0; n < 4; ++n)
            wmma::store_matrix_sync((float*)out + (size_t)grow0 * DD + n * 16,
                                    acc[n], DD, wmma::mem_row_major);
    }
}

// ---------------------------------------------------------------------------
// Inputs: 0 feats, 1 W0, 2 b0, 3 W1, 4 b1, 5 neigh_idx0, 6 neigh_idx1,
//         7 node_ids1 (unused), 8 node_ids2
// ---------------------------------------------------------------------------
extern "C" void kernel_launch(void* const* d_in, const int* in_sizes, int n_in,
                              void* d_out, int out_size)
{
    const float* feats      = (const float*)d_in[0];
    const float* W0         = (const float*)d_in[1];
    const float* b0         = (const float*)d_in[2];
    const float* W1         = (const float*)d_in[3];
    const float* b1         = (const float*)d_in[4];
    const int*   neigh_idx0 = (const int*)  d_in[5];
    const int*   neigh_idx1 = (const int*)  d_in[6];
    const int*   node_ids2  = (const int*)  d_in[8];
    float*       out        = (float*)d_out;

    __half* v2h;  cudaGetSymbolAddress((void**)&v2h,  g_v2h);
    __half* agg1; cudaGetSymbolAddress((void**)&agg1, g_agg1);
    __half* h1h;  cudaGetSymbolAddress((void**)&h1h,  g_h1h);
    __half* agg0; cudaGetSymbolAddress((void**)&agg0, g_agg0);
    __half* w0h;  cudaGetSymbolAddress((void**)&w0h,  g_W0h);
    __half* w1h;  cudaGetSymbolAddress((void**)&w1h,  g_W1h);

    cudaFuncSetAttribute(gemm_wmma_kernel<true>,
                         cudaFuncAttributeMaxDynamicSharedMemorySize, DYN_H);
    cudaFuncSetAttribute(gemm_wmma_kernel<false>,
                         cudaFuncAttributeMaxDynamicSharedMemorySize, DYN_F);

    convert_w_kernel<<<(DD * DD + 255) / 256, 256>>>(W0, W1);
    {
        const int half_total = (N2V / 2) * (DD / 4);
        gather_v2h_kernel<<<(half_total + 255) / 256, 256>>>(feats, node_ids2);
    }
    // Hop-1 aggregation + GEMM
    agg_mean_kernel<<<(N1V + 15) / 16, 256>>>(
        (const uint4*)v2h, neigh_idx1, agg1, N1V);
    gemm_wmma_kernel<true ><<<(N1V + 127) / 128, 256, DYN_H>>>(
        agg1, w0h, b0, (void*)h1h, N1V);
    // Seed aggregation + GEMM
    agg_mean_kernel<<<(N0V + 15) / 16, 256>>>(
        (const uint4*)h1h, neigh_idx0, agg0, N0V);
    gemm_wmma_kernel<false><<<N0V / 128, 256, DYN_F>>>(
        agg0, w1h, b1, (void*)out, N0V);
}